// round 1
// baseline (speedup 1.0000x reference)
#include <cuda_runtime.h>
#include <math.h>

// ---------------------------------------------------------------------------
// VPGNet forward, fp32. Shapes (batch 1):
//  x (3,480,640) -conv1 s4 k11-> (96,118,158) -LRN-> -pool3s2-> (96,58,78)
//  -upsample-> (96,59,79) -conv2 k5 p2-> (256,59,79) -LRN-> -pool-> (256,29,39)
//  -conv3 k3 p1-> (384,29,39) -conv4-> -conv5-> -pool-> (384,14,19)
//  -conv6 k6 p3-> (4096,15,20) = x6  [output 0]
//  branches: 1x1 4096->4096 relu; 1x1 4096->C8; tile(r)
// Output layout: [x6 | x8a | x8b | x8c | x8d] = 1,747,200 floats
// ---------------------------------------------------------------------------

// ---- scratch (__device__ globals: no allocation allowed) ----
__device__ float g_c1[96 * 118 * 158];
__device__ float g_l1[96 * 118 * 158];
__device__ float g_u1[96 * 59 * 79];
__device__ float g_c2[256 * 59 * 79];
__device__ float g_l2[256 * 59 * 79];
__device__ float g_p2[256 * 29 * 39];
__device__ float g_c3[384 * 29 * 39];
__device__ float g_c4[384 * 29 * 39];
__device__ float g_c5[384 * 29 * 39];
__device__ float g_p5[384 * 14 * 19];
__device__ float g_col[2400 * 4661];   // max im2col (conv2); conv6 needs 13824*300
__device__ float g_x7[4096 * 300];
__device__ float g_x8[1024 * 300];

// ---- conv1: 3->96, k=11, s=4, p=0, + ReLU ----
__global__ void k_conv1(const float* __restrict__ x, const float* __restrict__ w,
                        const float* __restrict__ b, float* __restrict__ out) {
    const int HO = 118, WO = 158;
    int i = blockIdx.x * blockDim.x + threadIdx.x;
    if (i >= 96 * HO * WO) return;
    int c = i / (HO * WO), r = i % (HO * WO), oh = r / WO, ow = r % WO;
    float acc = b[c];
    const float* wp = w + c * 3 * 121;
    for (int ci = 0; ci < 3; ci++) {
        const float* xc = x + ci * 480 * 640;
        const float* wc = wp + ci * 121;
        #pragma unroll
        for (int kh = 0; kh < 11; kh++) {
            const float* xp = xc + (oh * 4 + kh) * 640 + ow * 4;
            const float* wq = wc + kh * 11;
            #pragma unroll
            for (int kw = 0; kw < 11; kw++) acc = fmaf(xp[kw], wq[kw], acc);
        }
    }
    out[i] = fmaxf(acc, 0.f);
}

// ---- LRN: size=5, beta=0.75; out = in * (k + a*sum5 x^2)^-0.75 ----
__global__ void k_lrn(const float* __restrict__ in, float* __restrict__ out,
                      int C, int HW, float kconst, float a) {
    int i = blockIdx.x * blockDim.x + threadIdx.x;
    if (i >= C * HW) return;
    int c = i / HW, s = i % HW;
    int lo = c - 2 > 0 ? c - 2 : 0;
    int hi = c + 2 < C - 1 ? c + 2 : C - 1;
    float sum = 0.f;
    for (int j = lo; j <= hi; j++) { float v = in[j * HW + s]; sum = fmaf(v, v, sum); }
    out[i] = in[i] * powf(kconst + a * sum, -0.75f);
}

// ---- stage1 fused maxpool3s2 + nearest upsample (58,78)->(59,79) ----
__global__ void k_poolup(const float* __restrict__ in, float* __restrict__ out) {
    int i = blockIdx.x * blockDim.x + threadIdx.x;
    if (i >= 96 * 59 * 79) return;
    int c = i / (59 * 79), r = i % (59 * 79), oh = r / 79, ow = r % 79;
    int hi = (oh * 58) / 59, wi = (ow * 78) / 79;
    const float* p = in + (c * 118 + 2 * hi) * 158 + 2 * wi;
    float m = p[0];
    #pragma unroll
    for (int dh = 0; dh < 3; dh++)
        #pragma unroll
        for (int dw = 0; dw < 3; dw++) m = fmaxf(m, p[dh * 158 + dw]);
    out[i] = m;
}

// ---- generic maxpool 3x3 stride 2, VALID ----
__global__ void k_pool(const float* __restrict__ in, float* __restrict__ out,
                       int C, int Hin, int Win, int Ho, int Wo) {
    int i = blockIdx.x * blockDim.x + threadIdx.x;
    if (i >= C * Ho * Wo) return;
    int c = i / (Ho * Wo), r = i % (Ho * Wo), oh = r / Wo, ow = r % Wo;
    const float* p = in + (c * Hin + 2 * oh) * Win + 2 * ow;
    float m = p[0];
    #pragma unroll
    for (int dh = 0; dh < 3; dh++)
        #pragma unroll
        for (int dw = 0; dw < 3; dw++) m = fmaxf(m, p[dh * Win + dw]);
    out[i] = m;
}

// ---- im2col, stride 1, zero pad; out [C*k*k][Ho*Wo] row-major ----
__global__ void k_im2col(const float* __restrict__ in, float* __restrict__ out,
                         int C, int H, int W, int ksz, int pad, int Ho, int Wo) {
    int N = Ho * Wo;
    int total = C * ksz * ksz * N;
    int i = blockIdx.x * blockDim.x + threadIdx.x;
    if (i >= total) return;
    int n = i % N, kidx = i / N;
    int kw = kidx % ksz, t = kidx / ksz;
    int kh = t % ksz, c = t / ksz;
    int ow = n % Wo, oh = n / Wo;
    int ih = oh - pad + kh, iw = ow - pad + kw;
    float v = 0.f;
    if (ih >= 0 && ih < H && iw >= 0 && iw < W) v = in[(c * H + ih) * W + iw];
    out[i] = v;
}

// ---- tiled SGEMM: C[M,N] = A[M,K] @ B[K,N] + bias[M], optional ReLU ----
// BM=BN=64, BK=16, 256 threads, 4x4 per thread.
#define BM 64
#define BN 64
#define BK 16
__global__ __launch_bounds__(256) void k_gemm(
    const float* __restrict__ A, const float* __restrict__ B,
    const float* __restrict__ bias, float* __restrict__ C,
    int M, int N, int K, int relu) {
    __shared__ float As[BK][BM];
    __shared__ float Bs[BK][BN + 4];
    int tid = threadIdx.x;
    int tx = tid % 16, ty = tid / 16;
    int rowBase = blockIdx.y * BM, colBase = blockIdx.x * BN;
    float acc[4][4] = {};
    for (int k0 = 0; k0 < K; k0 += BK) {
        // A tile: 64 rows x 16 k  -> As[k][row]
        #pragma unroll
        for (int t = 0; t < 4; t++) {
            int e = tid + t * 256;           // 0..1023
            int i = e / BK, j = e % BK;
            int r = rowBase + i, c = k0 + j;
            As[j][i] = (r < M && c < K) ? A[(size_t)r * K + c] : 0.f;
        }
        // B tile: 16 k x 64 cols -> Bs[k][col]
        #pragma unroll
        for (int t = 0; t < 4; t++) {
            int e = tid + t * 256;
            int j = e / BN, i = e % BN;
            int r = k0 + j, c = colBase + i;
            Bs[j][i] = (r < K && c < N) ? B[(size_t)r * N + c] : 0.f;
        }
        __syncthreads();
        #pragma unroll
        for (int kk = 0; kk < BK; kk++) {
            float a[4], b[4];
            #pragma unroll
            for (int m = 0; m < 4; m++) a[m] = As[kk][ty * 4 + m];
            #pragma unroll
            for (int n = 0; n < 4; n++) b[n] = Bs[kk][tx * 4 + n];
            #pragma unroll
            for (int m = 0; m < 4; m++)
                #pragma unroll
                for (int n = 0; n < 4; n++) acc[m][n] = fmaf(a[m], b[n], acc[m][n]);
        }
        __syncthreads();
    }
    #pragma unroll
    for (int m = 0; m < 4; m++) {
        int r = rowBase + ty * 4 + m;
        if (r >= M) continue;
        float bv = bias[r];
        #pragma unroll
        for (int n = 0; n < 4; n++) {
            int c = colBase + tx * 4 + n;
            if (c >= N) continue;
            float v = acc[m][n] + bv;
            if (relu) v = fmaxf(v, 0.f);
            C[(size_t)r * N + c] = v;
        }
    }
}

// ---- pixel-shuffle tiling: in (C8,15,20) -> out (C8/r^2, 15r, 20r) ----
__global__ void k_tile(const float* __restrict__ in, float* __restrict__ out,
                       int C8, int r) {
    int total = C8 * 300;
    int i = blockIdx.x * blockDim.x + threadIdx.x;
    if (i >= total) return;
    int OH = 15 * r, OW = 20 * r;
    int oc = i / (OH * OW), rem = i % (OH * OW);
    int oh = rem / OW, ow = rem % OW;
    int ic = oc * r * r + (oh % r) * r + (ow % r);
    out[i] = in[ic * 300 + (oh / r) * 20 + (ow / r)];
}

static inline dim3 blk1(long n) { return dim3((unsigned)((n + 255) / 256)); }

extern "C" void kernel_launch(void* const* d_in, const int* in_sizes, int n_in,
                              void* d_out, int out_size) {
    const float* x  = (const float*)d_in[0];
    const float* w1 = (const float*)d_in[1];  const float* b1 = (const float*)d_in[2];
    const float* w2 = (const float*)d_in[3];  const float* b2 = (const float*)d_in[4];
    const float* w3 = (const float*)d_in[5];  const float* b3 = (const float*)d_in[6];
    const float* w4 = (const float*)d_in[7];  const float* b4 = (const float*)d_in[8];
    const float* w5 = (const float*)d_in[9];  const float* b5 = (const float*)d_in[10];
    const float* w6 = (const float*)d_in[11]; const float* b6 = (const float*)d_in[12];
    const float* w7[4] = {(const float*)d_in[13], (const float*)d_in[17],
                          (const float*)d_in[21], (const float*)d_in[25]};
    const float* b7[4] = {(const float*)d_in[14], (const float*)d_in[18],
                          (const float*)d_in[22], (const float*)d_in[26]};
    const float* w8[4] = {(const float*)d_in[15], (const float*)d_in[19],
                          (const float*)d_in[23], (const float*)d_in[27]};
    const float* b8[4] = {(const float*)d_in[16], (const float*)d_in[20],
                          (const float*)d_in[24], (const float*)d_in[28]};
    float* out = (float*)d_out;

    float *c1, *l1, *u1, *c2, *l2, *p2, *c3, *c4, *c5, *p5, *col, *x7, *x8;
    cudaGetSymbolAddress((void**)&c1, g_c1);
    cudaGetSymbolAddress((void**)&l1, g_l1);
    cudaGetSymbolAddress((void**)&u1, g_u1);
    cudaGetSymbolAddress((void**)&c2, g_c2);
    cudaGetSymbolAddress((void**)&l2, g_l2);
    cudaGetSymbolAddress((void**)&p2, g_p2);
    cudaGetSymbolAddress((void**)&c3, g_c3);
    cudaGetSymbolAddress((void**)&c4, g_c4);
    cudaGetSymbolAddress((void**)&c5, g_c5);
    cudaGetSymbolAddress((void**)&p5, g_p5);
    cudaGetSymbolAddress((void**)&col, g_col);
    cudaGetSymbolAddress((void**)&x7, g_x7);
    cudaGetSymbolAddress((void**)&x8, g_x8);

    // stage 1
    k_conv1<<<blk1(96L * 118 * 158), 256>>>(x, w1, b1, c1);
    k_lrn<<<blk1(96L * 118 * 158), 256>>>(c1, l1, 96, 118 * 158, 2.0f, 0.0001f);
    k_poolup<<<blk1(96L * 59 * 79), 256>>>(l1, u1);

    // conv2 (k5 p2): im2col + GEMM, N=59*79=4661, K=2400
    k_im2col<<<blk1(2400L * 4661), 256>>>(u1, col, 96, 59, 79, 5, 2, 59, 79);
    k_gemm<<<dim3((4661 + 63) / 64, 256 / 64), 256>>>(w2, col, b2, c2, 256, 4661, 2400, 1);
    k_lrn<<<blk1(256L * 4661), 256>>>(c2, l2, 256, 4661, 8.0f, 0.0001f);
    k_pool<<<blk1(256L * 29 * 39), 256>>>(l2, p2, 256, 59, 79, 29, 39);

    // conv3 (k3 p1): N=29*39=1131, K=2304
    k_im2col<<<blk1(2304L * 1131), 256>>>(p2, col, 256, 29, 39, 3, 1, 29, 39);
    k_gemm<<<dim3((1131 + 63) / 64, 384 / 64), 256>>>(w3, col, b3, c3, 384, 1131, 2304, 1);
    // conv4: K=3456
    k_im2col<<<blk1(3456L * 1131), 256>>>(c3, col, 384, 29, 39, 3, 1, 29, 39);
    k_gemm<<<dim3((1131 + 63) / 64, 384 / 64), 256>>>(w4, col, b4, c4, 384, 1131, 3456, 1);
    // conv5
    k_im2col<<<blk1(3456L * 1131), 256>>>(c4, col, 384, 29, 39, 3, 1, 29, 39);
    k_gemm<<<dim3((1131 + 63) / 64, 384 / 64), 256>>>(w5, col, b5, c5, 384, 1131, 3456, 1);
    k_pool<<<blk1(384L * 14 * 19), 256>>>(c5, p5, 384, 29, 39, 14, 19);

    // conv6 (k6 p3): N=15*20=300, K=13824 -> x6 straight into d_out[0..1228800)
    k_im2col<<<blk1(13824L * 300), 256>>>(p5, col, 384, 14, 19, 6, 3, 15, 20);
    k_gemm<<<dim3((300 + 63) / 64, 4096 / 64), 256>>>(w6, col, b6, out, 4096, 300, 13824, 1);

    // branches: 1x1 convs are plain GEMMs over N=300; x6 lives in d_out
    const int  C8s[4]  = {256, 128, 1024, 320};
    const int  rs[4]   = {8, 8, 4, 8};
    const long offs[4] = {1228800L, 1228800L + 76800L, 1228800L + 76800L + 38400L,
                          1228800L + 76800L + 38400L + 307200L};
    for (int t = 0; t < 4; t++) {
        k_gemm<<<dim3((300 + 63) / 64, 4096 / 64), 256>>>(w7[t], out, b7[t], x7,
                                                          4096, 300, 4096, 1);
        k_gemm<<<dim3((300 + 63) / 64, C8s[t] / 64), 256>>>(w8[t], x7, b8[t], x8,
                                                            C8s[t], 300, 4096, 0);
        k_tile<<<blk1((long)C8s[t] * 300), 256>>>(x8, out + offs[t], C8s[t], rs[t]);
    }
}

// round 3
// speedup vs baseline: 3.1366x; 3.1366x over previous
#include <cuda_runtime.h>
#include <cuda_bf16.h>
#include <math.h>
#include <stdint.h>

// ---------------------------------------------------------------------------
// VPGNet forward. Conv GEMMs via warp-level mma.sync bf16 (2-term split,
// fp32 accumulate). Output: [x6 | x8a | x8b | x8c | x8d] = 1,747,200 floats
// ---------------------------------------------------------------------------

// ---- scratch (__device__ globals: no allocation allowed) ----
__device__ float g_c1[96 * 118 * 158];
__device__ float g_l1[96 * 118 * 158];
__device__ float g_u1[96 * 59 * 79];
__device__ float g_c2[256 * 59 * 79];
__device__ float g_l2[256 * 59 * 79];
__device__ float g_p2[256 * 29 * 39];
__device__ float g_c3[384 * 29 * 39];
__device__ float g_c4[384 * 29 * 39];
__device__ float g_c5[384 * 29 * 39];
__device__ float g_p5[384 * 14 * 19];
__device__ float g_x7[4096 * 300];
__device__ float g_x8[1024 * 300];
// bf16 split activation buffers [Npad][Kpad]; max conv2: 4672*2400 = 11,212,800
__device__ __nv_bfloat16 gB_hi[11250000];
__device__ __nv_bfloat16 gB_lo[11250000];
// dedicated split of x6 (reused by all 4 branches)
__device__ __nv_bfloat16 gB6_hi[320 * 4096];
__device__ __nv_bfloat16 gB6_lo[320 * 4096];

// ============================ helpers ============================
__device__ __forceinline__ uint32_t smem_u32(const void* p) {
    uint32_t a;
    asm("{ .reg .u64 t; cvta.to.shared.u64 t, %1; cvt.u32.u64 %0, t; }" : "=r"(a) : "l"(p));
    return a;
}
// SW64-style swizzle for 64-byte-pitch rows: XOR 16B-chunk bits [4:5] with row bits (o bits 7:8)
__device__ __forceinline__ uint32_t swz64(uint32_t o) { return o ^ ((o >> 3) & 0x30); }

__device__ __forceinline__ void ldm4(uint32_t* r, uint32_t a) {
    asm volatile("ldmatrix.sync.aligned.m8n8.x4.shared.b16 {%0,%1,%2,%3}, [%4];"
                 : "=r"(r[0]), "=r"(r[1]), "=r"(r[2]), "=r"(r[3]) : "r"(a));
}
__device__ __forceinline__ void mma_bf16(float* c, const uint32_t* a, const uint32_t* b) {
    asm volatile("mma.sync.aligned.m16n8k16.row.col.f32.bf16.bf16.f32 "
                 "{%0,%1,%2,%3}, {%4,%5,%6,%7}, {%8,%9}, {%0,%1,%2,%3};"
                 : "+f"(c[0]), "+f"(c[1]), "+f"(c[2]), "+f"(c[3])
                 : "r"(a[0]), "r"(a[1]), "r"(a[2]), "r"(a[3]), "r"(b[0]), "r"(b[1]));
}
__device__ __forceinline__ void sts128(uint32_t a, uint4 v) {
    asm volatile("st.shared.v4.b32 [%0], {%1,%2,%3,%4};"
                 :: "r"(a), "r"(v.x), "r"(v.y), "r"(v.z), "r"(v.w) : "memory");
}
__device__ __forceinline__ void sts64(uint32_t a, uint32_t x, uint32_t y) {
    asm volatile("st.shared.v2.b32 [%0], {%1,%2};" :: "r"(a), "r"(x), "r"(y) : "memory");
}
__device__ __forceinline__ uint32_t packbf2(float lo, float hi) {
    uint32_t d;
    asm("cvt.rn.bf16x2.f32 %0, %1, %2;" : "=r"(d) : "f"(hi), "f"(lo));
    return d;
}

// ============================ small layers ============================
__global__ void k_conv1(const float* __restrict__ x, const float* __restrict__ w,
                        const float* __restrict__ b, float* __restrict__ out) {
    const int HO = 118, WO = 158;
    int i = blockIdx.x * blockDim.x + threadIdx.x;
    if (i >= 96 * HO * WO) return;
    int c = i / (HO * WO), r = i % (HO * WO), oh = r / WO, ow = r % WO;
    float acc = b[c];
    const float* wp = w + c * 3 * 121;
    for (int ci = 0; ci < 3; ci++) {
        const float* xc = x + ci * 480 * 640;
        const float* wc = wp + ci * 121;
        #pragma unroll
        for (int kh = 0; kh < 11; kh++) {
            const float* xp = xc + (oh * 4 + kh) * 640 + ow * 4;
            const float* wq = wc + kh * 11;
            #pragma unroll
            for (int kw = 0; kw < 11; kw++) acc = fmaf(xp[kw], wq[kw], acc);
        }
    }
    out[i] = fmaxf(acc, 0.f);
}

__global__ void k_lrn(const float* __restrict__ in, float* __restrict__ out,
                      int C, int HW, float kconst, float a) {
    int i = blockIdx.x * blockDim.x + threadIdx.x;
    if (i >= C * HW) return;
    int c = i / HW, s = i % HW;
    int lo = c - 2 > 0 ? c - 2 : 0;
    int hi = c + 2 < C - 1 ? c + 2 : C - 1;
    float sum = 0.f;
    for (int j = lo; j <= hi; j++) { float v = in[j * HW + s]; sum = fmaf(v, v, sum); }
    out[i] = in[i] * powf(kconst + a * sum, -0.75f);
}

__global__ void k_poolup(const float* __restrict__ in, float* __restrict__ out) {
    int i = blockIdx.x * blockDim.x + threadIdx.x;
    if (i >= 96 * 59 * 79) return;
    int c = i / (59 * 79), r = i % (59 * 79), oh = r / 79, ow = r % 79;
    int hi = (oh * 58) / 59, wi = (ow * 78) / 79;
    const float* p = in + (c * 118 + 2 * hi) * 158 + 2 * wi;
    float m = p[0];
    #pragma unroll
    for (int dh = 0; dh < 3; dh++)
        #pragma unroll
        for (int dw = 0; dw < 3; dw++) m = fmaxf(m, p[dh * 158 + dw]);
    out[i] = m;
}

__global__ void k_pool(const float* __restrict__ in, float* __restrict__ out,
                       int C, int Hin, int Win, int Ho, int Wo) {
    int i = blockIdx.x * blockDim.x + threadIdx.x;
    if (i >= C * Ho * Wo) return;
    int c = i / (Ho * Wo), r = i % (Ho * Wo), oh = r / Wo, ow = r % Wo;
    const float* p = in + (c * Hin + 2 * oh) * Win + 2 * ow;
    float m = p[0];
    #pragma unroll
    for (int dh = 0; dh < 3; dh++)
        #pragma unroll
        for (int dw = 0; dw < 3; dw++) m = fmaxf(m, p[dh * Win + dw]);
    out[i] = m;
}

__global__ void k_tile(const float* __restrict__ in, float* __restrict__ out,
                       int C8, int r) {
    int total = C8 * 300;
    int i = blockIdx.x * blockDim.x + threadIdx.x;
    if (i >= total) return;
    int OH = 15 * r, OW = 20 * r;
    int oc = i / (OH * OW), rem = i % (OH * OW);
    int oh = rem / OW, ow = rem % OW;
    int ic = oc * r * r + (oh % r) * r + (ow % r);
    out[i] = in[ic * 300 + (oh / r) * 20 + (ow / r)];
}

// ---- fused im2col + transpose + bf16 split:  src (C,H,W) -> [Npad][K] hi/lo
__global__ void k_prepB(const float* __restrict__ src, __nv_bfloat16* __restrict__ hi,
                        __nv_bfloat16* __restrict__ lo, int Cc, int H, int W,
                        int ksz, int pad, int Ho, int Wo, int Kreal,
                        long total) {
    long i = blockIdx.x * (long)blockDim.x + threadIdx.x;
    if (i >= total) return;
    int kidx = (int)(i % Kreal);
    int n = (int)(i / Kreal);
    float v = 0.f;
    if (n < Ho * Wo) {
        int kw = kidx % ksz;
        int t = kidx / ksz;
        int kh = t % ksz, cc = t / ksz;
        int oh = n / Wo, ow = n % Wo;
        int ih = oh - pad + kh, iw = ow - pad + kw;
        if (ih >= 0 && ih < H && iw >= 0 && iw < W) v = src[((size_t)cc * H + ih) * W + iw];
    }
    __nv_bfloat16 h = __float2bfloat16(v);
    hi[i] = h;
    lo[i] = __float2bfloat16(v - __bfloat162float(h));
}

// ============================ HMMA GEMM ============================
// C[M,Ncols] = A[M,K](fp32, split in-kernel) @ B^T, B pre-split bf16 [Npad][K].
// CTA tile 128x64, BK=32, 8 warps (4m x 2n), warp tile 32x32.
// Stage layout (24KB): Ah[128x32] 8K | Al 8K | Bh[64x32] 4K | Bl 4K. 2 stages.
#define STG 24576
#define GT_SMEM (2 * STG + 1024)
__global__ __launch_bounds__(256, 2) void k_gemm_tc(
    const float* __restrict__ A, const __nv_bfloat16* __restrict__ Bh,
    const __nv_bfloat16* __restrict__ Bl, const float* __restrict__ bias,
    float* __restrict__ C, int M, int K, int Ncols, int relu) {
    extern __shared__ char dsm[];
    const int tid = threadIdx.x;
    const int lane = tid & 31;
    const int wid = tid >> 5;
    const int wm = wid & 3, wn = wid >> 2;
    const int m0 = blockIdx.y * 128;
    const int n0 = blockIdx.x * 64;

    const uint32_t base = (smem_u32(dsm) + 1023u) & ~1023u;

    // ---- per-thread global load coords ----
    // A: idx = tid + it*256 (it<4): row = idx>>3, f4 = idx&7  (k = f4*4)
    // B: it 0 (hi) / 1 (lo): r = tid>>2, f = tid&3            (k = f*8)
    const int aRow = tid >> 3, aF4 = tid & 7;
    const int bR = tid >> 2, bF = tid & 3;

    // ---- per-thread ldmatrix smem offsets (pre-swizzled, XOR kb later) ----
    uint32_t pA[2], pB[2];
    {
        uint32_t r = (uint32_t)(wm * 32 + (lane & 15));
        uint32_t kc = (uint32_t)((lane >> 4) * 16);
        #pragma unroll
        for (int mt = 0; mt < 2; mt++) {
            uint32_t o = (r + mt * 16) * 64 + kc;
            pA[mt] = o ^ ((o >> 3) & 0x30);
        }
        uint32_t rn = (uint32_t)(wn * 32 + (lane & 7) + ((lane >> 4) << 3));
        uint32_t kcb = (uint32_t)(((lane >> 3) & 1) * 16);
        #pragma unroll
        for (int nt = 0; nt < 2; nt++) {
            uint32_t o = (rn + nt * 16) * 64 + kcb;
            pB[nt] = o ^ ((o >> 3) & 0x30);
        }
    }

    float acc[2][4][4] = {};
    const int nc = K >> 5;

    // ---- prefetch chunk 0 ----
    float4 aP[4];
    uint4 bP[2];
    {
        #pragma unroll
        for (int it = 0; it < 4; it++) {
            int idx = tid + it * 256;
            int row = idx >> 3, f4 = idx & 7;
            int gr = m0 + row;
            aP[it] = (gr < M) ? *reinterpret_cast<const float4*>(A + (size_t)gr * K + f4 * 4)
                              : make_float4(0.f, 0.f, 0.f, 0.f);
        }
        bP[0] = *reinterpret_cast<const uint4*>(Bh + (size_t)(n0 + bR) * K + bF * 8);
        bP[1] = *reinterpret_cast<const uint4*>(Bl + (size_t)(n0 + bR) * K + bF * 8);
    }

    for (int c = 0; c < nc; c++) {
        const uint32_t stg = base + (uint32_t)(c & 1) * STG;
        // ---- store prefetched chunk to smem (split A) ----
        #pragma unroll
        for (int it = 0; it < 4; it++) {
            int idx = tid + it * 256;
            int row = idx >> 3, f4 = idx & 7;
            float4 v = aP[it];
            __nv_bfloat16 h0 = __float2bfloat16(v.x), h1 = __float2bfloat16(v.y),
                          h2 = __float2bfloat16(v.z), h3 = __float2bfloat16(v.w);
            float l0 = v.x - __bfloat162float(h0), l1 = v.y - __bfloat162float(h1);
            float l2 = v.z - __bfloat162float(h2), l3 = v.w - __bfloat162float(h3);
            uint32_t off = swz64((uint32_t)(row * 64 + f4 * 8));
            sts64(stg + off, packbf2(__bfloat162float(h0), __bfloat162float(h1)),
                             packbf2(__bfloat162float(h2), __bfloat162float(h3)));
            sts64(stg + 8192u + off, packbf2(l0, l1), packbf2(l2, l3));
        }
        {
            uint32_t off = swz64((uint32_t)(bR * 64 + bF * 16));
            sts128(stg + 16384u + off, bP[0]);
            sts128(stg + 20480u + off, bP[1]);
        }
        __syncthreads();
        // ---- prefetch next chunk ----
        if (c + 1 < nc) {
            const int k0 = (c + 1) << 5;
            #pragma unroll
            for (int it = 0; it < 4; it++) {
                int idx = tid + it * 256;
                int row = idx >> 3, f4 = idx & 7;
                int gr = m0 + row;
                aP[it] = (gr < M)
                    ? *reinterpret_cast<const float4*>(A + (size_t)gr * K + k0 + f4 * 4)
                    : make_float4(0.f, 0.f, 0.f, 0.f);
            }
            bP[0] = *reinterpret_cast<const uint4*>(Bh + (size_t)(n0 + bR) * K + k0 + bF * 8);
            bP[1] = *reinterpret_cast<const uint4*>(Bl + (size_t)(n0 + bR) * K + k0 + bF * 8);
        }
        // ---- compute on current stage ----
        #pragma unroll
        for (int ks = 0; ks < 2; ks++) {
            const uint32_t kb = (uint32_t)(ks << 5);
            uint32_t ah[2][4], al[2][4], bh_[2][4], bl_[2][4];
            ldm4(ah[0], stg + (pA[0] ^ kb));
            ldm4(ah[1], stg + (pA[1] ^ kb));
            ldm4(al[0], stg + 8192u + (pA[0] ^ kb));
            ldm4(al[1], stg + 8192u + (pA[1] ^ kb));
            ldm4(bh_[0], stg + 16384u + (pB[0] ^ kb));
            ldm4(bh_[1], stg + 16384u + (pB[1] ^ kb));
            ldm4(bl_[0], stg + 20480u + (pB[0] ^ kb));
            ldm4(bl_[1], stg + 20480u + (pB[1] ^ kb));
            #pragma unroll
            for (int mt = 0; mt < 2; mt++)
                #pragma unroll
                for (int nt = 0; nt < 4; nt++) {
                    const uint32_t* bh2 = &bh_[nt >> 1][(nt & 1) * 2];
                    const uint32_t* bl2 = &bl_[nt >> 1][(nt & 1) * 2];
                    mma_bf16(acc[mt][nt], ah[mt], bh2);
                    mma_bf16(acc[mt][nt], ah[mt], bl2);
                    mma_bf16(acc[mt][nt], al[mt], bh2);
                }
        }
        __syncthreads();
    }

    // ---- epilogue ----
    #pragma unroll
    for (int mt = 0; mt < 2; mt++) {
        int r0 = m0 + wm * 32 + mt * 16 + (lane >> 2);
        #pragma unroll
        for (int half = 0; half < 2; half++) {
            int row = r0 + half * 8;
            if (row >= M) continue;
            float bv = bias[row];
            #pragma unroll
            for (int nt = 0; nt < 4; nt++) {
                int col = n0 + wn * 32 + nt * 8 + (lane & 3) * 2;
                float v0 = acc[mt][nt][half * 2 + 0] + bv;
                float v1 = acc[mt][nt][half * 2 + 1] + bv;
                if (relu) { v0 = fmaxf(v0, 0.f); v1 = fmaxf(v1, 0.f); }
                if (col < Ncols) C[(size_t)row * Ncols + col] = v0;
                if (col + 1 < Ncols) C[(size_t)row * Ncols + col + 1] = v1;
            }
        }
    }
}

static inline dim3 blk1(long n) { return dim3((unsigned)((n + 255) / 256)); }

extern "C" void kernel_launch(void* const* d_in, const int* in_sizes, int n_in,
                              void* d_out, int out_size) {
    const float* x  = (const float*)d_in[0];
    const float* w1 = (const float*)d_in[1];  const float* b1 = (const float*)d_in[2];
    const float* w2 = (const float*)d_in[3];  const float* b2 = (const float*)d_in[4];
    const float* w3 = (const float*)d_in[5];  const float* b3 = (const float*)d_in[6];
    const float* w4 = (const float*)d_in[7];  const float* b4 = (const float*)d_in[8];
    const float* w5 = (const float*)d_in[9];  const float* b5 = (const float*)d_in[10];
    const float* w6 = (const float*)d_in[11]; const float* b6 = (const float*)d_in[12];
    const float* w7[4] = {(const float*)d_in[13], (const float*)d_in[17],
                          (const float*)d_in[21], (const float*)d_in[25]};
    const float* b7[4] = {(const float*)d_in[14], (const float*)d_in[18],
                          (const float*)d_in[22], (const float*)d_in[26]};
    const float* w8[4] = {(const float*)d_in[15], (const float*)d_in[19],
                          (const float*)d_in[23], (const float*)d_in[27]};
    const float* b8[4] = {(const float*)d_in[16], (const float*)d_in[20],
                          (const float*)d_in[24], (const float*)d_in[28]};
    float* out = (float*)d_out;

    cudaFuncSetAttribute(k_gemm_tc, cudaFuncAttributeMaxDynamicSharedMemorySize, GT_SMEM);

    float *c1, *l1, *u1, *c2, *l2, *p2, *c3, *c4, *c5, *p5, *x7, *x8;
    __nv_bfloat16 *bh, *bl, *b6h, *b6l;
    cudaGetSymbolAddress((void**)&c1, g_c1);
    cudaGetSymbolAddress((void**)&l1, g_l1);
    cudaGetSymbolAddress((void**)&u1, g_u1);
    cudaGetSymbolAddress((void**)&c2, g_c2);
    cudaGetSymbolAddress((void**)&l2, g_l2);
    cudaGetSymbolAddress((void**)&p2, g_p2);
    cudaGetSymbolAddress((void**)&c3, g_c3);
    cudaGetSymbolAddress((void**)&c4, g_c4);
    cudaGetSymbolAddress((void**)&c5, g_c5);
    cudaGetSymbolAddress((void**)&p5, g_p5);
    cudaGetSymbolAddress((void**)&x7, g_x7);
    cudaGetSymbolAddress((void**)&x8, g_x8);
    cudaGetSymbolAddress((void**)&bh, gB_hi);
    cudaGetSymbolAddress((void**)&bl, gB_lo);
    cudaGetSymbolAddress((void**)&b6h, gB6_hi);
    cudaGetSymbolAddress((void**)&b6l, gB6_lo);

    // stage 1 (direct fp32)
    k_conv1<<<blk1(96L * 118 * 158), 256>>>(x, w1, b1, c1);
    k_lrn<<<blk1(96L * 118 * 158), 256>>>(c1, l1, 96, 118 * 158, 2.0f, 0.0001f);
    k_poolup<<<blk1(96L * 59 * 79), 256>>>(l1, u1);

    // conv2: M=256 K=2400 N=4661 (Npad 4672)
    k_prepB<<<blk1(4672L * 2400), 256>>>(u1, bh, bl, 96, 59, 79, 5, 2, 59, 79,
                                         2400, 4672L * 2400);
    k_gemm_tc<<<dim3(73, 2), 256, GT_SMEM>>>(w2, bh, bl, b2, c2, 256, 2400, 4661, 1);
    k_lrn<<<blk1(256L * 4661), 256>>>(c2, l2, 256, 4661, 8.0f, 0.0001f);
    k_pool<<<blk1(256L * 29 * 39), 256>>>(l2, p2, 256, 59, 79, 29, 39);

    // conv3: M=384 K=2304 N=1131 (Npad 1152)
    k_prepB<<<blk1(1152L * 2304), 256>>>(p2, bh, bl, 256, 29, 39, 3, 1, 29, 39,
                                         2304, 1152L * 2304);
    k_gemm_tc<<<dim3(18, 3), 256, GT_SMEM>>>(w3, bh, bl, b3, c3, 384, 2304, 1131, 1);
    // conv4: K=3456
    k_prepB<<<blk1(1152L * 3456), 256>>>(c3, bh, bl, 384, 29, 39, 3, 1, 29, 39,
                                         3456, 1152L * 3456);
    k_gemm_tc<<<dim3(18, 3), 256, GT_SMEM>>>(w4, bh, bl, b4, c4, 384, 3456, 1131, 1);
    // conv5
    k_prepB<<<blk1(1152L * 3456), 256>>>(c4, bh, bl, 384, 29, 39, 3, 1, 29, 39,
                                         3456, 1152L * 3456);
    k_gemm_tc<<<dim3(18, 3), 256, GT_SMEM>>>(w5, bh, bl, b5, c5, 384, 3456, 1131, 1);
    k_pool<<<blk1(384L * 14 * 19), 256>>>(c5, p5, 384, 29, 39, 14, 19);

    // conv6: M=4096 K=13824 N=300 (Npad 320) -> x6 straight into d_out
    k_prepB<<<blk1(320L * 13824), 256>>>(p5, bh, bl, 384, 14, 19, 6, 3, 15, 20,
                                         13824, 320L * 13824);
    k_gemm_tc<<<dim3(5, 32), 256, GT_SMEM>>>(w6, bh, bl, b6, out, 4096, 13824, 300, 1);

    // split x6 once (1x1 conv: C=4096 over 15x20)
    k_prepB<<<blk1(320L * 4096), 256>>>(out, b6h, b6l, 4096, 15, 20, 1, 0, 15, 20,
                                        4096, 320L * 4096);

    const int  C8s[4]  = {256, 128, 1024, 320};
    const int  rs[4]   = {8, 8, 4, 8};
    const long offs[4] = {1228800L, 1228800L + 76800L, 1228800L + 76800L + 38400L,
                          1228800L + 76800L + 38400L + 307200L};
    for (int t = 0; t < 4; t++) {
        k_gemm_tc<<<dim3(5, 32), 256, GT_SMEM>>>(w7[t], b6h, b6l, b7[t], x7,
                                                 4096, 4096, 300, 1);
        k_prepB<<<blk1(320L * 4096), 256>>>(x7, bh, bl, 4096, 15, 20, 1, 0, 15, 20,
                                            4096, 320L * 4096);
        k_gemm_tc<<<dim3(5, (C8s[t] + 127) / 128), 256, GT_SMEM>>>(
            w8[t], bh, bl, b8[t], x8, C8s[t], 4096, 300, 0);
        k_tile<<<blk1((long)C8s[t] * 300), 256>>>(x8, out + offs[t], C8s[t], rs[t]);
    }
}